// round 6
// baseline (speedup 1.0000x reference)
#include <cuda_runtime.h>
#include <cuda_fp16.h>

#define BSZ    2048
#define TT     128
#define NN     256
#define MM     256
#define GG4    1024
#define B_TILE 16
#define NBLK   (BSZ / B_TILE)  /* 128 */
#define NTHR   512

// ---------------- device scratch ----------------
__device__ __half g_Ux[(size_t)BSZ * TT * NN];       // [b][s][n] fp16, 134 MB
__device__ float4 g_Wt [128 * 1024];                 // [k4][r] : float4 = 4 consecutive k of row r (r = g*256+m)
__device__ float4 g_WtE[128 * 128];                  // [k4][s] : float4 = 4 consecutive k of W_e row s

// ---------------- fast math ----------------
__device__ __forceinline__ float ex2f(float x) {
    float r; asm("ex2.approx.f32 %0, %1;" : "=f"(r) : "f"(x)); return r;
}
__device__ __forceinline__ float rcpf(float x) {
    float r; asm("rcp.approx.f32 %0, %1;" : "=f"(r) : "f"(x)); return r;
}
#define L2E 1.4426950408889634f
__device__ __forceinline__ float tanh_fast(float x) {      // precise path (cell update)
    float t = ex2f(2.0f * L2E * x);
    return 1.0f - 2.0f * rcpf(t + 1.0f);
}
__device__ __forceinline__ float sigmoid_fast(float x) {
    return rcpf(1.0f + ex2f(-L2E * x));
}
__device__ __forceinline__ unsigned tanh2_h(unsigned x) {  // f16x2 hw tanh (attention only)
    unsigned r; asm("tanh.approx.f16x2 %0, %1;" : "=r"(r) : "r"(x)); return r;
}

// ---------------- packed f32x2 ----------------
typedef unsigned long long u64;
__device__ __forceinline__ u64 pack2(float a, float b) {
    u64 r; asm("mov.b64 %0, {%1, %2};" : "=l"(r) : "f"(a), "f"(b)); return r;
}
__device__ __forceinline__ void unpack2(u64 v, float& a, float& b) {
    asm("mov.b64 {%0, %1}, %2;" : "=f"(a), "=f"(b) : "l"(v));
}
__device__ __forceinline__ u64 ffma2(u64 a, u64 b, u64 c) {
    u64 d; asm("fma.rn.f32x2 %0, %1, %2, %3;" : "=l"(d) : "l"(a), "l"(b), "l"(c)); return d;
}
__device__ __forceinline__ float pair_sum(u64 v) {
    float a, b; unpack2(v, a, b); return a + b;
}

// =====================================================================
// Kernel 0: weight transpose -> k-major float4 tiles
// =====================================================================
__global__ void __launch_bounds__(256) wt_kernel(
    const float* __restrict__ W_ih, const float* __restrict__ W_hh,
    const float* __restrict__ W_e)
{
    int idx = blockIdx.x * 256 + threadIdx.x;
    if (idx < 128 * 1024) {
        int k4 = idx >> 10, r = idx & 1023;
        float4 v = (k4 < 64) ? ((const float4*)W_ih)[r * 64 + k4]
                             : ((const float4*)W_hh)[r * 64 + (k4 - 64)];
        g_Wt[idx] = v;
    } else {
        int j = idx - 128 * 1024;          // 0..16383
        int k4 = j >> 7, s = j & 127;
        g_WtE[j] = ((const float4*)W_e)[s * 128 + k4];
    }
}

// =====================================================================
// Kernel 1: Ux[b][s][n] = sum_t U_e[s][t] * x[b][t][n]  (fp16 output)
// =====================================================================
__global__ void __launch_bounds__(256, 1) ux_kernel(
    const float* __restrict__ x, const float* __restrict__ U_e)
{
    extern __shared__ float sm[];
    float* x_s  = sm;                    // [TT][NN]
    u64*   U2_s = (u64*)(sm + TT * NN);  // [64 s-pairs][128 t]
    float* U2f  = (float*)U2_s;

    const int b   = blockIdx.x;
    const int tid = threadIdx.x;

    const float4* xg = (const float4*)(x + (size_t)b * TT * NN);
    float4* xs4 = (float4*)x_s;
    for (int i = tid; i < TT * NN / 4; i += 256) xs4[i] = xg[i];

    for (int i = tid; i < TT * TT / 4; i += 256) {
        float4 v = ((const float4*)U_e)[i];
        int s  = i >> 5;
        int t0 = (i & 31) * 4;
        #pragma unroll
        for (int q = 0; q < 4; q++)
            U2f[(((s >> 1) * 128) + (t0 + q)) * 2 + (s & 1)] = (&v.x)[q];
    }
    __syncthreads();

    const int n = tid;
    for (int chunk = 0; chunk < 8; chunk++) {
        u64 acc[8];
        #pragma unroll
        for (int i = 0; i < 8; i++) acc[i] = 0ull;
        #pragma unroll 2
        for (int t = 0; t < TT; t++) {
            float xv = x_s[t * NN + n];
            u64 xp = pack2(xv, xv);
            #pragma unroll
            for (int i = 0; i < 8; i++)
                acc[i] = ffma2(U2_s[(chunk * 8 + i) * 128 + t], xp, acc[i]);
        }
        #pragma unroll
        for (int i = 0; i < 8; i++) {
            float a, bb; unpack2(acc[i], a, bb);
            #pragma unroll
            for (int h = 0; h < 2; h++) {
                float v = h ? bb : a;
                int s = chunk * 16 + 2 * i + h;
                float vn = __shfl_down_sync(0xffffffffu, v, 1);
                if ((n & 1) == 0) {
                    __half2 hv = __floats2half2_rn(v, vn);
                    *((__half2*)(g_Ux + ((size_t)b * TT + s) * NN + n)) = hv;
                }
            }
        }
    }
}

// =====================================================================
// Kernel 2: persistent recurrence. 128 blocks x 16 batches, 512 threads.
// State layout is j-major [j][k] so phase A/D read natural k-pairs.
// =====================================================================
__global__ void __launch_bounds__(NTHR, 1) rec_kernel(
    const float* __restrict__ V_e,
    const float* __restrict__ b_ih, const float* __restrict__ b_hh,
    float* __restrict__ out)
{
    extern __shared__ float sm[];
    float*    h_s   = sm;                      // [B_TILE][NN]
    float*    c_s   = h_s  + B_TILE * NN;      // [B_TILE][NN]
    float*    ex_s  = c_s  + B_TILE * NN;      // [B_TILE][NN]  e, then xt in place
    float*    bs_s  = ex_s + B_TILE * NN;      // [GG4]
    float*    V_s   = bs_s + GG4;              // [TT]
    unsigned* whs2  = (unsigned*)(V_s + TT);   // [TT][B_TILE] half2(w,w)

    const int tid = threadIdx.x;
    const int b0  = blockIdx.x * B_TILE;

    for (int i = tid; i < 2 * B_TILE * NN; i += NTHR) h_s[i] = 0.0f;  // h_s + c_s
    for (int i = tid; i < TT;  i += NTHR) V_s[i]  = V_e[i];
    for (int i = tid; i < GG4; i += NTHR) bs_s[i] = b_ih[i] + b_hh[i];
    __syncthreads();

    // phase A: thread = (sI, 4 batches)
    const int sI  = tid & 127;
    const int j0A = (tid >> 7) * 4;
    // phase B: thread = (n-pair, 4 batches); jg is warp-uniform
    const int np  = tid & 127;
    const int n0  = np * 2;
    const int jg  = tid >> 7;                  // 0..3
    // phase C: warp = batch
    const int warp = tid >> 5, lane = tid & 31;
    // phase D: thread = (m, 8 batches)
    const int mD  = tid & 255;
    const int jD0 = (tid >> 8) * 8;

    const __half2* ux2[4];
    #pragma unroll
    for (int jj = 0; jj < 4; jj++)
        ux2[jj] = (const __half2*)(g_Ux + ((size_t)(b0 + jg * 4 + jj) * TT) * NN + n0);

    for (int t = 0; t < TT; t++) {
        // ---------- Phase A: whs[sI][j] = [h;c] . W_e[sI]  (k-paired f32x2) ----------
        {
            u64 acc[4] = {0ull, 0ull, 0ull, 0ull};
            #pragma unroll 2
            for (int k4 = 0; k4 < 64; k4++) {
                ulonglong2 wp = *(const ulonglong2*)&g_WtE[k4 * 128 + sI];
                #pragma unroll
                for (int jj = 0; jj < 4; jj++) {
                    ulonglong2 sp = *(const ulonglong2*)&h_s[(j0A + jj) * NN + k4 * 4];
                    acc[jj] = ffma2(wp.x, sp.x, acc[jj]);
                    acc[jj] = ffma2(wp.y, sp.y, acc[jj]);
                }
            }
            #pragma unroll 2
            for (int k4 = 64; k4 < 128; k4++) {
                ulonglong2 wp = *(const ulonglong2*)&g_WtE[k4 * 128 + sI];
                #pragma unroll
                for (int jj = 0; jj < 4; jj++) {
                    ulonglong2 sp = *(const ulonglong2*)&c_s[(j0A + jj) * NN + (k4 - 64) * 4];
                    acc[jj] = ffma2(wp.x, sp.x, acc[jj]);
                    acc[jj] = ffma2(wp.y, sp.y, acc[jj]);
                }
            }
            #pragma unroll
            for (int jj = 0; jj < 4; jj++) {
                __half2 p = __half2half2(__float2half_rn(pair_sum(acc[jj])));
                whs2[sI * B_TILE + j0A + jj] = *(unsigned*)&p;
            }
        }
        __syncthreads();

        // ---------- Phase B: e[j][n] = sum_s V[s] * tanh(Ux + whs)  (fp16 stream) ----------
        {
            float ex0[4] = {0, 0, 0, 0}, ex1[4] = {0, 0, 0, 0};
            #pragma unroll 2
            for (int s = 0; s < TT; s++) {
                uint4 wpk = *(const uint4*)&whs2[s * B_TILE + jg * 4];  // broadcast
                float vs = V_s[s];
                #pragma unroll
                for (int jj = 0; jj < 4; jj++) {
                    __half2 u   = ux2[jj][s * (NN / 2)];
                    __half2 wv  = *(__half2*)(((unsigned*)&wpk) + jj);
                    __half2 arg = __hadd2(u, wv);
                    unsigned th = tanh2_h(*(unsigned*)&arg);
                    float2 f = __half22float2(*(__half2*)&th);
                    ex0[jj] = fmaf(vs, f.x, ex0[jj]);
                    ex1[jj] = fmaf(vs, f.y, ex1[jj]);
                }
            }
            #pragma unroll
            for (int jj = 0; jj < 4; jj++) {
                float2 v = make_float2(ex0[jj], ex1[jj]);
                *(float2*)&ex_s[(jg * 4 + jj) * NN + n0] = v;
            }
        }
        __syncthreads();

        // ---------- Phase C: softmax over n, xt = alpha * e  (in place) ----------
        {
            const int j = warp;
            float ev[8];
            float mx = -3.4e38f;
            #pragma unroll
            for (int i = 0; i < 8; i++) {
                ev[i] = ex_s[j * NN + lane + 32 * i];
                mx = fmaxf(mx, ev[i]);
            }
            #pragma unroll
            for (int o = 16; o > 0; o >>= 1) mx = fmaxf(mx, __shfl_xor_sync(0xffffffffu, mx, o));
            float ax[8], sum = 0.0f;
            #pragma unroll
            for (int i = 0; i < 8; i++) { ax[i] = ex2f((ev[i] - mx) * L2E); sum += ax[i]; }
            #pragma unroll
            for (int o = 16; o > 0; o >>= 1) sum += __shfl_xor_sync(0xffffffffu, sum, o);
            float inv = rcpf(sum);
            #pragma unroll
            for (int i = 0; i < 8; i++)
                ex_s[j * NN + lane + 32 * i] = (ax[i] * inv) * ev[i];
        }
        __syncthreads();

        // ---------- Phase D: gates = [W_ih W_hh] @ [xt; h] + bias  (k-paired f32x2) ----------
        {
            u64 acc[4][8];
            #pragma unroll
            for (int g = 0; g < 4; g++) {
                u64 bp = pack2(bs_s[g * MM + mD], 0.0f);
                #pragma unroll
                for (int jj = 0; jj < 8; jj++) acc[g][jj] = bp;
            }
            const float4* wr = g_Wt + mD;
            // k < 256 : xt part
            #pragma unroll 2
            for (int k4 = 0; k4 < 64; k4++) {
                ulonglong2 w0 = *(const ulonglong2*)&wr[k4 * 1024 +   0];
                ulonglong2 w1 = *(const ulonglong2*)&wr[k4 * 1024 + 256];
                ulonglong2 w2 = *(const ulonglong2*)&wr[k4 * 1024 + 512];
                ulonglong2 w3 = *(const ulonglong2*)&wr[k4 * 1024 + 768];
                #pragma unroll
                for (int jj = 0; jj < 8; jj++) {
                    ulonglong2 sp = *(const ulonglong2*)&ex_s[(jD0 + jj) * NN + k4 * 4];
                    acc[0][jj] = ffma2(w0.x, sp.x, acc[0][jj]);
                    acc[0][jj] = ffma2(w0.y, sp.y, acc[0][jj]);
                    acc[1][jj] = ffma2(w1.x, sp.x, acc[1][jj]);
                    acc[1][jj] = ffma2(w1.y, sp.y, acc[1][jj]);
                    acc[2][jj] = ffma2(w2.x, sp.x, acc[2][jj]);
                    acc[2][jj] = ffma2(w2.y, sp.y, acc[2][jj]);
                    acc[3][jj] = ffma2(w3.x, sp.x, acc[3][jj]);
                    acc[3][jj] = ffma2(w3.y, sp.y, acc[3][jj]);
                }
            }
            // k >= 256 : h part
            #pragma unroll 2
            for (int k4 = 64; k4 < 128; k4++) {
                ulonglong2 w0 = *(const ulonglong2*)&wr[k4 * 1024 +   0];
                ulonglong2 w1 = *(const ulonglong2*)&wr[k4 * 1024 + 256];
                ulonglong2 w2 = *(const ulonglong2*)&wr[k4 * 1024 + 512];
                ulonglong2 w3 = *(const ulonglong2*)&wr[k4 * 1024 + 768];
                #pragma unroll
                for (int jj = 0; jj < 8; jj++) {
                    ulonglong2 sp = *(const ulonglong2*)&h_s[(jD0 + jj) * NN + (k4 - 64) * 4];
                    acc[0][jj] = ffma2(w0.x, sp.x, acc[0][jj]);
                    acc[0][jj] = ffma2(w0.y, sp.y, acc[0][jj]);
                    acc[1][jj] = ffma2(w1.x, sp.x, acc[1][jj]);
                    acc[1][jj] = ffma2(w1.y, sp.y, acc[1][jj]);
                    acc[2][jj] = ffma2(w2.x, sp.x, acc[2][jj]);
                    acc[2][jj] = ffma2(w2.y, sp.y, acc[2][jj]);
                    acc[3][jj] = ffma2(w3.x, sp.x, acc[3][jj]);
                    acc[3][jj] = ffma2(w3.y, sp.y, acc[3][jj]);
                }
            }
            float cold[8];
            #pragma unroll
            for (int jj = 0; jj < 8; jj++) cold[jj] = c_s[(jD0 + jj) * NN + mD];
            __syncthreads();   // all reads of h_s/ex_s/c_s complete before writes

            #pragma unroll
            for (int jj = 0; jj < 8; jj++) {
                float iv = pair_sum(acc[0][jj]);
                float fv = pair_sum(acc[1][jj]);
                float gv = pair_sum(acc[2][jj]);
                float ov = pair_sum(acc[3][jj]);
                float cn = sigmoid_fast(fv) * cold[jj] + sigmoid_fast(iv) * tanh_fast(gv);
                float hn = sigmoid_fast(ov) * tanh_fast(cn);
                c_s[(jD0 + jj) * NN + mD] = cn;
                h_s[(jD0 + jj) * NN + mD] = hn;
                out[(size_t)(b0 + jD0 + jj) * (MM * TT) + (size_t)mD * TT + t] = hn;
            }
        }
        __syncthreads();   // state visible before next step
    }
}

extern "C" void kernel_launch(void* const* d_in, const int* in_sizes, int n_in,
                              void* d_out, int out_size)
{
    const float* x    = (const float*)d_in[0];
    const float* W_e  = (const float*)d_in[1];
    const float* U_e  = (const float*)d_in[2];
    const float* V_e  = (const float*)d_in[3];
    const float* W_ih = (const float*)d_in[4];
    const float* W_hh = (const float*)d_in[5];
    const float* b_ih = (const float*)d_in[6];
    const float* b_hh = (const float*)d_in[7];
    float* out = (float*)d_out;

    const int smem1 = (TT * NN) * 4 + 64 * 128 * 8;                        // 196608
    const int smem2 = (3 * B_TILE * NN + GG4 + TT) * 4 + TT * B_TILE * 4;  // ~62 KB

    cudaFuncSetAttribute(ux_kernel,  cudaFuncAttributeMaxDynamicSharedMemorySize, smem1);
    cudaFuncSetAttribute(rec_kernel, cudaFuncAttributeMaxDynamicSharedMemorySize, smem2);

    wt_kernel<<<(128 * 1024 + 128 * 128) / 256, 256>>>(W_ih, W_hh, W_e);
    ux_kernel<<<BSZ, 256, smem1>>>(x, U_e);
    rec_kernel<<<NBLK, NTHR, smem2>>>(V_e, b_ih, b_hh, out);
}

// round 8
// speedup vs baseline: 1.1138x; 1.1138x over previous
#include <cuda_runtime.h>
#include <cuda_fp16.h>

#define BSZ    2048
#define TT     128
#define NN     256
#define MM     256
#define GG4    1024
#define B_TILE 16
#define NBLK   (BSZ / B_TILE)  /* 128 */
#define NTHR   512

// ---------------- device scratch ----------------
__device__ __half g_Ux[(size_t)BSZ * TT * NN];       // [b][s][n] fp16, 134 MB
__device__ float4 g_Wt [128 * 1024];                 // [k4][r] : 4 consecutive k of row r (r = g*256+m)
__device__ float4 g_WtE[128 * 128];                  // [k4][s] : 4 consecutive k of W_e row s

// ---------------- fast math ----------------
__device__ __forceinline__ float ex2f(float x) {
    float r; asm("ex2.approx.f32 %0, %1;" : "=f"(r) : "f"(x)); return r;
}
__device__ __forceinline__ float rcpf(float x) {
    float r; asm("rcp.approx.f32 %0, %1;" : "=f"(r) : "f"(x)); return r;
}
#define L2E 1.4426950408889634f
__device__ __forceinline__ float tanh_fast(float x) {      // precise path (cell update)
    float t = ex2f(2.0f * L2E * x);
    return 1.0f - 2.0f * rcpf(t + 1.0f);
}
__device__ __forceinline__ float sigmoid_fast(float x) {
    return rcpf(1.0f + ex2f(-L2E * x));
}
__device__ __forceinline__ unsigned tanh2_h(unsigned x) {  // f16x2 hw tanh (attention only)
    unsigned r; asm("tanh.approx.f16x2 %0, %1;" : "=r"(r) : "r"(x)); return r;
}

// ---------------- packed f32x2 ----------------
typedef unsigned long long u64;
__device__ __forceinline__ u64 pack2(float a, float b) {
    u64 r; asm("mov.b64 %0, {%1, %2};" : "=l"(r) : "f"(a), "f"(b)); return r;
}
__device__ __forceinline__ void unpack2(u64 v, float& a, float& b) {
    asm("mov.b64 {%0, %1}, %2;" : "=f"(a), "=f"(b) : "l"(v));
}
__device__ __forceinline__ u64 ffma2(u64 a, u64 b, u64 c) {
    u64 d; asm("fma.rn.f32x2 %0, %1, %2, %3;" : "=l"(d) : "l"(a), "l"(b), "l"(c)); return d;
}
__device__ __forceinline__ float pair_sum(u64 v) {
    float a, b; unpack2(v, a, b); return a + b;
}

// =====================================================================
// Kernel 1: Ux precompute (+ weight transpose in trailing blocks).
// Blocks [0, BSZ): Ux[b][s][n] = sum_t U_e[s][t] * x[b][t][n]  (fp16 out)
// Blocks [BSZ, BSZ+576): k-major weight transpose into g_Wt / g_WtE.
// =====================================================================
__global__ void __launch_bounds__(256, 1) ux_kernel(
    const float* __restrict__ x,    const float* __restrict__ U_e,
    const float* __restrict__ W_ih, const float* __restrict__ W_hh,
    const float* __restrict__ W_e)
{
    if (blockIdx.x >= BSZ) {   // ---- transpose duty ----
        int idx = (blockIdx.x - BSZ) * 256 + threadIdx.x;
        if (idx < 128 * 1024) {
            int k4 = idx >> 10, r = idx & 1023;
            float4 v = (k4 < 64) ? ((const float4*)W_ih)[r * 64 + k4]
                                 : ((const float4*)W_hh)[r * 64 + (k4 - 64)];
            g_Wt[idx] = v;
        } else {
            int j = idx - 128 * 1024;      // 0..16383
            int k4 = j >> 7, s = j & 127;
            g_WtE[j] = ((const float4*)W_e)[s * 128 + k4];
        }
        return;
    }

    extern __shared__ float sm[];
    float* x_s  = sm;                    // [TT][NN]
    u64*   U2_s = (u64*)(sm + TT * NN);  // [64 s-pairs][128 t]
    float* U2f  = (float*)U2_s;

    const int b   = blockIdx.x;
    const int tid = threadIdx.x;

    const float4* xg = (const float4*)(x + (size_t)b * TT * NN);
    float4* xs4 = (float4*)x_s;
    for (int i = tid; i < TT * NN / 4; i += 256) xs4[i] = xg[i];

    for (int i = tid; i < TT * TT / 4; i += 256) {
        float4 v = ((const float4*)U_e)[i];
        int s  = i >> 5;
        int t0 = (i & 31) * 4;
        #pragma unroll
        for (int q = 0; q < 4; q++)
            U2f[(((s >> 1) * 128) + (t0 + q)) * 2 + (s & 1)] = (&v.x)[q];
    }
    __syncthreads();

    const int n = tid;
    for (int chunk = 0; chunk < 8; chunk++) {
        u64 acc[8];
        #pragma unroll
        for (int i = 0; i < 8; i++) acc[i] = 0ull;
        #pragma unroll 2
        for (int t = 0; t < TT; t++) {
            float xv = x_s[t * NN + n];
            u64 xp = pack2(xv, xv);
            #pragma unroll
            for (int i = 0; i < 8; i++)
                acc[i] = ffma2(U2_s[(chunk * 8 + i) * 128 + t], xp, acc[i]);
        }
        #pragma unroll
        for (int i = 0; i < 8; i++) {
            float a, bb; unpack2(acc[i], a, bb);
            #pragma unroll
            for (int h = 0; h < 2; h++) {
                float v = h ? bb : a;
                int s = chunk * 16 + 2 * i + h;
                float vn = __shfl_down_sync(0xffffffffu, v, 1);
                if ((n & 1) == 0) {
                    __half2 hv = __floats2half2_rn(v, vn);
                    *((__half2*)(g_Ux + ((size_t)b * TT + s) * NN + n)) = hv;
                }
            }
        }
    }
}

// =====================================================================
// Kernel 2: persistent recurrence. 128 blocks x 16 batches, 512 threads.
// State j-major [j][k]; phase D gate-split into 2 passes (reg pressure).
// =====================================================================
__global__ void __launch_bounds__(NTHR, 1) rec_kernel(
    const float* __restrict__ V_e,
    const float* __restrict__ b_ih, const float* __restrict__ b_hh,
    float* __restrict__ out)
{
    extern __shared__ float sm[];
    float*    h_s   = sm;                      // [B_TILE][NN]
    float*    c_s   = h_s  + B_TILE * NN;      // [B_TILE][NN]
    float*    ex_s  = c_s  + B_TILE * NN;      // [B_TILE][NN]  e, then xt in place
    float*    bs_s  = ex_s + B_TILE * NN;      // [GG4]
    float*    V_s   = bs_s + GG4;              // [TT]
    unsigned* whs2  = (unsigned*)(V_s + TT);   // [TT][B_TILE] half2(w,w)

    const int tid = threadIdx.x;
    const int b0  = blockIdx.x * B_TILE;

    for (int i = tid; i < 2 * B_TILE * NN; i += NTHR) h_s[i] = 0.0f;  // h_s + c_s
    for (int i = tid; i < TT;  i += NTHR) V_s[i]  = V_e[i];
    for (int i = tid; i < GG4; i += NTHR) bs_s[i] = b_ih[i] + b_hh[i];
    __syncthreads();

    // phase A: thread = (sI, 4 batches)
    const int sI  = tid & 127;
    const int j0A = (tid >> 7) * 4;
    // phase B: thread = (n-pair, 4 batches); jg warp-uniform
    const int np  = tid & 127;
    const int n0  = np * 2;
    const int jg  = tid >> 7;                  // 0..3
    // phase C: warp = batch
    const int warp = tid >> 5, lane = tid & 31;
    // phase D: thread = (m, 8 batches)
    const int mD  = tid & 255;
    const int jD0 = (tid >> 8) * 8;

    const __half2* ux2[4];
    #pragma unroll
    for (int jj = 0; jj < 4; jj++)
        ux2[jj] = (const __half2*)(g_Ux + ((size_t)(b0 + jg * 4 + jj) * TT) * NN + n0);

    const float4* wr = g_Wt + mD;

    for (int t = 0; t < TT; t++) {
        // ---------- Phase A: whs[sI][j] = [h;c] . W_e[sI]  (k-paired f32x2) ----------
        {
            u64 acc[4] = {0ull, 0ull, 0ull, 0ull};
            #pragma unroll 2
            for (int k4 = 0; k4 < 64; k4++) {
                ulonglong2 wp = *(const ulonglong2*)&g_WtE[k4 * 128 + sI];
                #pragma unroll
                for (int jj = 0; jj < 4; jj++) {
                    ulonglong2 sp = *(const ulonglong2*)&h_s[(j0A + jj) * NN + k4 * 4];
                    acc[jj] = ffma2(wp.x, sp.x, acc[jj]);
                    acc[jj] = ffma2(wp.y, sp.y, acc[jj]);
                }
            }
            #pragma unroll 2
            for (int k4 = 64; k4 < 128; k4++) {
                ulonglong2 wp = *(const ulonglong2*)&g_WtE[k4 * 128 + sI];
                #pragma unroll
                for (int jj = 0; jj < 4; jj++) {
                    ulonglong2 sp = *(const ulonglong2*)&c_s[(j0A + jj) * NN + (k4 - 64) * 4];
                    acc[jj] = ffma2(wp.x, sp.x, acc[jj]);
                    acc[jj] = ffma2(wp.y, sp.y, acc[jj]);
                }
            }
            #pragma unroll
            for (int jj = 0; jj < 4; jj++) {
                __half2 p = __half2half2(__float2half_rn(pair_sum(acc[jj])));
                whs2[sI * B_TILE + j0A + jj] = *(unsigned*)&p;
            }
        }
        __syncthreads();

        // ---------- Phase B: e[j][n] = sum_s V[s] * tanh(Ux + whs)  (fp16 stream) ----------
        {
            float ex0[4] = {0, 0, 0, 0}, ex1[4] = {0, 0, 0, 0};
            #pragma unroll 2
            for (int s = 0; s < TT; s++) {
                uint4 wpk = *(const uint4*)&whs2[s * B_TILE + jg * 4];  // broadcast
                float vs = V_s[s];
                #pragma unroll
                for (int jj = 0; jj < 4; jj++) {
                    __half2 u   = ux2[jj][s * (NN / 2)];
                    __half2 wv  = *(__half2*)(((unsigned*)&wpk) + jj);
                    __half2 arg = __hadd2(u, wv);
                    unsigned th = tanh2_h(*(unsigned*)&arg);
                    float2 f = __half22float2(*(__half2*)&th);
                    ex0[jj] = fmaf(vs, f.x, ex0[jj]);
                    ex1[jj] = fmaf(vs, f.y, ex1[jj]);
                }
            }
            #pragma unroll
            for (int jj = 0; jj < 4; jj++) {
                float2 v = make_float2(ex0[jj], ex1[jj]);
                *(float2*)&ex_s[(jg * 4 + jj) * NN + n0] = v;
            }
        }
        __syncthreads();

        // ---------- Phase C: softmax over n, xt = alpha * e  (in place) ----------
        {
            const int j = warp;
            float ev[8];
            float mx = -3.4e38f;
            #pragma unroll
            for (int i = 0; i < 8; i++) {
                ev[i] = ex_s[j * NN + lane + 32 * i];
                mx = fmaxf(mx, ev[i]);
            }
            #pragma unroll
            for (int o = 16; o > 0; o >>= 1) mx = fmaxf(mx, __shfl_xor_sync(0xffffffffu, mx, o));
            float ax[8], sum = 0.0f;
            #pragma unroll
            for (int i = 0; i < 8; i++) { ax[i] = ex2f((ev[i] - mx) * L2E); sum += ax[i]; }
            #pragma unroll
            for (int o = 16; o > 0; o >>= 1) sum += __shfl_xor_sync(0xffffffffu, sum, o);
            float inv = rcpf(sum);
            #pragma unroll
            for (int i = 0; i < 8; i++)
                ex_s[j * NN + lane + 32 * i] = (ax[i] * inv) * ev[i];
        }
        __syncthreads();

        // ---------- Phase D: gates, two gate-pair passes (acc = 32 regs/pass) ----------
        {
            float giv[8], gfv[8], ggv[8], gov[8];

            // pass 1: gates i (rows 0..255) and f (rows 256..511)
            {
                u64 a0[8], a1[8];
                u64 bi = pack2(bs_s[0 * MM + mD], 0.0f);
                u64 bf = pack2(bs_s[1 * MM + mD], 0.0f);
                #pragma unroll
                for (int jj = 0; jj < 8; jj++) { a0[jj] = bi; a1[jj] = bf; }
                #pragma unroll 4
                for (int k4 = 0; k4 < 64; k4++) {
                    ulonglong2 w0 = *(const ulonglong2*)&wr[k4 * 1024 +   0];
                    ulonglong2 w1 = *(const ulonglong2*)&wr[k4 * 1024 + 256];
                    #pragma unroll
                    for (int jj = 0; jj < 8; jj++) {
                        ulonglong2 sp = *(const ulonglong2*)&ex_s[(jD0 + jj) * NN + k4 * 4];
                        a0[jj] = ffma2(w0.x, sp.x, a0[jj]);
                        a0[jj] = ffma2(w0.y, sp.y, a0[jj]);
                        a1[jj] = ffma2(w1.x, sp.x, a1[jj]);
                        a1[jj] = ffma2(w1.y, sp.y, a1[jj]);
                    }
                }
                #pragma unroll 4
                for (int k4 = 64; k4 < 128; k4++) {
                    ulonglong2 w0 = *(const ulonglong2*)&wr[k4 * 1024 +   0];
                    ulonglong2 w1 = *(const ulonglong2*)&wr[k4 * 1024 + 256];
                    #pragma unroll
                    for (int jj = 0; jj < 8; jj++) {
                        ulonglong2 sp = *(const ulonglong2*)&h_s[(jD0 + jj) * NN + (k4 - 64) * 4];
                        a0[jj] = ffma2(w0.x, sp.x, a0[jj]);
                        a0[jj] = ffma2(w0.y, sp.y, a0[jj]);
                        a1[jj] = ffma2(w1.x, sp.x, a1[jj]);
                        a1[jj] = ffma2(w1.y, sp.y, a1[jj]);
                    }
                }
                #pragma unroll
                for (int jj = 0; jj < 8; jj++) { giv[jj] = pair_sum(a0[jj]); gfv[jj] = pair_sum(a1[jj]); }
            }

            // pass 2: gates g (rows 512..767) and o (rows 768..1023)
            {
                u64 a0[8], a1[8];
                u64 bg = pack2(bs_s[2 * MM + mD], 0.0f);
                u64 bo = pack2(bs_s[3 * MM + mD], 0.0f);
                #pragma unroll
                for (int jj = 0; jj < 8; jj++) { a0[jj] = bg; a1[jj] = bo; }
                #pragma unroll 4
                for (int k4 = 0; k4 < 64; k4++) {
                    ulonglong2 w0 = *(const ulonglong2*)&wr[k4 * 1024 + 512];
                    ulonglong2 w1 = *(const ulonglong2*)&wr[k4 * 1024 + 768];
                    #pragma unroll
                    for (int jj = 0; jj < 8; jj++) {
                        ulonglong2 sp = *(const ulonglong2*)&ex_s[(jD0 + jj) * NN + k4 * 4];
                        a0[jj] = ffma2(w0.x, sp.x, a0[jj]);
                        a0[jj] = ffma2(w0.y, sp.y, a0[jj]);
                        a1[jj] = ffma2(w1.x, sp.x, a1[jj]);
                        a1[jj] = ffma2(w1.y, sp.y, a1[jj]);
                    }
                }
                #pragma unroll 4
                for (int k4 = 64; k4 < 128; k4++) {
                    ulonglong2 w0 = *(const ulonglong2*)&wr[k4 * 1024 + 512];
                    ulonglong2 w1 = *(const ulonglong2*)&wr[k4 * 1024 + 768];
                    #pragma unroll
                    for (int jj = 0; jj < 8; jj++) {
                        ulonglong2 sp = *(const ulonglong2*)&h_s[(jD0 + jj) * NN + (k4 - 64) * 4];
                        a0[jj] = ffma2(w0.x, sp.x, a0[jj]);
                        a0[jj] = ffma2(w0.y, sp.y, a0[jj]);
                        a1[jj] = ffma2(w1.x, sp.x, a1[jj]);
                        a1[jj] = ffma2(w1.y, sp.y, a1[jj]);
                    }
                }
                #pragma unroll
                for (int jj = 0; jj < 8; jj++) { ggv[jj] = pair_sum(a0[jj]); gov[jj] = pair_sum(a1[jj]); }
            }

            float cold[8];
            #pragma unroll
            for (int jj = 0; jj < 8; jj++) cold[jj] = c_s[(jD0 + jj) * NN + mD];
            __syncthreads();   // all reads of h_s/ex_s/c_s complete before writes

            #pragma unroll
            for (int jj = 0; jj < 8; jj++) {
                float cn = sigmoid_fast(gfv[jj]) * cold[jj]
                         + sigmoid_fast(giv[jj]) * tanh_fast(ggv[jj]);
                float hn = sigmoid_fast(gov[jj]) * tanh_fast(cn);
                c_s[(jD0 + jj) * NN + mD] = cn;
                h_s[(jD0 + jj) * NN + mD] = hn;
                out[(size_t)(b0 + jD0 + jj) * (MM * TT) + (size_t)mD * TT + t] = hn;
            }
        }
        __syncthreads();   // state visible before next step
    }
}

extern "C" void kernel_launch(void* const* d_in, const int* in_sizes, int n_in,
                              void* d_out, int out_size)
{
    const float* x    = (const float*)d_in[0];
    const float* W_e  = (const float*)d_in[1];
    const float* U_e  = (const float*)d_in[2];
    const float* V_e  = (const float*)d_in[3];
    const float* W_ih = (const float*)d_in[4];
    const float* W_hh = (const float*)d_in[5];
    const float* b_ih = (const float*)d_in[6];
    const float* b_hh = (const float*)d_in[7];
    float* out = (float*)d_out;

    const int smem1 = (TT * NN) * 4 + 64 * 128 * 8;                        // 196608
    const int smem2 = (3 * B_TILE * NN + GG4 + TT) * 4 + TT * B_TILE * 4;  // ~62 KB

    cudaFuncSetAttribute(ux_kernel,  cudaFuncAttributeMaxDynamicSharedMemorySize, smem1);
    cudaFuncSetAttribute(rec_kernel, cudaFuncAttributeMaxDynamicSharedMemorySize, smem2);

    ux_kernel<<<BSZ + 576, 256, smem1>>>(x, U_e, W_ih, W_hh, W_e);
    rec_kernel<<<NBLK, NTHR, smem2>>>(V_e, b_ih, b_hh, out);
}